// round 10
// baseline (speedup 1.0000x reference)
#include <cuda_runtime.h>
#include <cuda_bf16.h>
#include <cuda_fp8.h>
#include <math.h>
#include <stdint.h>

// ---------------- problem constants ----------------
#define HH    320
#define WW    320
#define DIM   256
#define WIN   10
#define NH    8
#define HD    32
#define NTOK  (HH*WW)            // 102400
#define NWIN  (32*32)            // 1024
#define NN    (WIN*WIN)          // 100
#define MROWS NTOK
#define HID   1024
#define SCALE 0.17677669529663687f
#define LNEPS 1e-5f

typedef __nv_bfloat16 bf16;

// ---------------- scratch ----------------
__device__ unsigned g_winw[MROWS*128];   // LN1 out bf16x2, window order
__device__ unsigned g_qw  [MROWS*128];   // Q (scaled) bf16x2
__device__ unsigned g_kvw [MROWS*256];   // K | V bf16x2
__device__ unsigned g_ow  [MROWS*128];   // attention out bf16x2, window order
__device__ float    g_x2  [MROWS*256];   // x + attn branch (fp32, token order)
__device__ uint8_t  g_h2b [MROWS*256];   // LN2 out, e4m3
__device__ unsigned g_fw  [MROWS*512];   // gelu(h2@l1+b) bf16x2, NHWC (dwconv input)
__device__ uint8_t  g_f2b [MROWS*1024];  // gelu(dwconv+b), e4m3

// weights: bf16 [K][N] for QKV/proj; e4m3 transposed [N][K] for L1/L2
__device__ bf16    p_qkvB[256*768];
__device__ bf16    p_projB[256*256];
__device__ uint8_t p_l1F8[1024*256];     // [n][k]
__device__ uint8_t p_l2F8[256*1024];     // [n][k]

__device__ __forceinline__ float gelu_exact(float v) {
    return 0.5f * v * (1.0f + erff(v * 0.70710678118654752f));
}
__device__ __forceinline__ unsigned packbf(float a, float b) {
    __nv_bfloat162 t = __floats2bfloat162_rn(a, b);
    return *(unsigned*)&t;
}
__device__ __forceinline__ float2 unpackbf(unsigned u) {
    return __bfloat1622float2(*(__nv_bfloat162*)&u);
}
// e4m3 pair: lo in low byte  (PTX cvt packs first operand into upper half)
__device__ __forceinline__ unsigned short pack8(float lo, float hi) {
    unsigned short r;
    asm("cvt.rn.satfinite.e4m3x2.f32 %0, %1, %2;" : "=h"(r) : "f"(hi), "f"(lo));
    return r;
}
__device__ __forceinline__ void mma_bf16(float c[4], unsigned a0, unsigned a1,
                                         unsigned a2, unsigned a3,
                                         unsigned b0, unsigned b1) {
    asm volatile("mma.sync.aligned.m16n8k16.row.col.f32.bf16.bf16.f32 "
                 "{%0,%1,%2,%3}, {%4,%5,%6,%7}, {%8,%9}, {%0,%1,%2,%3};"
                 : "+f"(c[0]), "+f"(c[1]), "+f"(c[2]), "+f"(c[3])
                 : "r"(a0), "r"(a1), "r"(a2), "r"(a3), "r"(b0), "r"(b1));
}
__device__ __forceinline__ void mma_fp8(float c[4], const unsigned a[4],
                                        unsigned b0, unsigned b1) {
    asm volatile("mma.sync.aligned.m16n8k32.row.col.f32.e4m3.e4m3.f32 "
                 "{%0,%1,%2,%3}, {%4,%5,%6,%7}, {%8,%9}, {%0,%1,%2,%3};"
                 : "+f"(c[0]), "+f"(c[1]), "+f"(c[2]), "+f"(c[3])
                 : "r"(a[0]), "r"(a[1]), "r"(a[2]), "r"(a[3]), "r"(b0), "r"(b1));
}
__device__ __forceinline__ void cp16(void* smem, const void* g) {
    unsigned s = (unsigned)__cvta_generic_to_shared(smem);
    asm volatile("cp.async.cg.shared.global [%0], [%1], 16;" :: "r"(s), "l"(g));
}
__device__ __forceinline__ void ldm_x4(unsigned& r0, unsigned& r1, unsigned& r2,
                                       unsigned& r3, const void* p) {
    unsigned s = (unsigned)__cvta_generic_to_shared(p);
    asm volatile("ldmatrix.sync.aligned.m8n8.x4.shared.b16 {%0,%1,%2,%3}, [%4];"
                 : "=r"(r0), "=r"(r1), "=r"(r2), "=r"(r3) : "r"(s));
}

// ---------------- weight pack ----------------
__global__ void pack_all(const float* __restrict__ wq, const float* __restrict__ wkv,
                         const float* __restrict__ proj_w, const float* __restrict__ l1_w,
                         const float* __restrict__ l2_w) {
    int i = blockIdx.x * 256 + threadIdx.x;
    if (i < 196608) {                     // qkvB [256][768] bf16
        int k = i / 768, n = i - k * 768;
        float v = (n < 256) ? wq[k * 256 + n] : wkv[k * 512 + (n - 256)];
        p_qkvB[i] = __float2bfloat16(v);
    } else if (i < 262144) {              // projB [256][256] bf16
        int j = i - 196608;
        p_projB[j] = __float2bfloat16(proj_w[j]);
    } else if (i < 524288) {              // l1F8 [n=1024][k=256] e4m3, coalesced writes
        int j = i - 262144, n = j >> 8, k = j & 255;
        unsigned short s = pack8(l1_w[(size_t)k * 1024 + n], 0.f);
        p_l1F8[j] = (uint8_t)(s & 0xFF);
    } else if (i < 786432) {              // l2F8 [n=256][k=1024] e4m3
        int j = i - 524288, n = j >> 10, k = j & 1023;
        unsigned short s = pack8(l2_w[(size_t)k * 256 + n], 0.f);
        p_l2F8[j] = (uint8_t)(s & 0xFF);
    }
}

// ---------------- LayerNorm: warp per token ----------------
template<int M>   // M=0: x -> g_winw (window perm, bf16); M=1: g_x2 -> g_h2b (e4m3)
__global__ __launch_bounds__(256)
void ln_kernel(const float* __restrict__ xin,
               const float* __restrict__ g, const float* __restrict__ b) {
    int warp = threadIdx.x >> 5, lane = threadIdx.x & 31;
    int t = blockIdx.x * 8 + warp;
    const float* src = (M == 0) ? xin : g_x2;
    const float4* xp = (const float4*)(src + (size_t)t * DIM) + lane * 2;
    float4 f0 = xp[0], f1 = xp[1];
    float s  = f0.x + f0.y + f0.z + f0.w + f1.x + f1.y + f1.z + f1.w;
    float ss = f0.x*f0.x + f0.y*f0.y + f0.z*f0.z + f0.w*f0.w
             + f1.x*f1.x + f1.y*f1.y + f1.z*f1.z + f1.w*f1.w;
    #pragma unroll
    for (int o = 16; o; o >>= 1) {
        s  += __shfl_xor_sync(0xffffffffu, s,  o);
        ss += __shfl_xor_sync(0xffffffffu, ss, o);
    }
    float mean = s * (1.0f / DIM);
    float rstd = rsqrtf(ss * (1.0f / DIM) - mean * mean + LNEPS);
    const float4* gp = (const float4*)g + lane * 2;
    const float4* bp = (const float4*)b + lane * 2;
    float4 g0 = gp[0], g1 = gp[1], b0 = bp[0], b1 = bp[1];
    float y0 = (f0.x-mean)*rstd*g0.x + b0.x, y1 = (f0.y-mean)*rstd*g0.y + b0.y;
    float y2 = (f0.z-mean)*rstd*g0.z + b0.z, y3 = (f0.w-mean)*rstd*g0.w + b0.w;
    float y4 = (f1.x-mean)*rstd*g1.x + b1.x, y5 = (f1.y-mean)*rstd*g1.y + b1.y;
    float y6 = (f1.z-mean)*rstd*g1.z + b1.z, y7 = (f1.w-mean)*rstd*g1.w + b1.w;
    if constexpr (M == 0) {
        int h = t / WW, w = t - h * WW;
        size_t r = ((h / WIN) * 32 + (w / WIN)) * NN + (h % WIN) * WIN + (w % WIN);
        *(uint4*)&g_winw[r * 128 + lane * 4] =
            make_uint4(packbf(y0, y1), packbf(y2, y3), packbf(y4, y5), packbf(y6, y7));
    } else {
        unsigned lo = (unsigned)pack8(y0, y1) | ((unsigned)pack8(y2, y3) << 16);
        unsigned hi = (unsigned)pack8(y4, y5) | ((unsigned)pack8(y6, y7) << 16);
        *(uint2*)&g_h2b[(size_t)t * 256 + lane * 8] = make_uint2(lo, hi);
    }
}

// ---------------- bf16 MMA GEMM (round-8, unchanged): QKV + proj ----------------
#define TG_SMEM 65536

template<int MODE>  // 0: qkv, 2: proj
__launch_bounds__(256)
__global__ void tgemm(const bf16* __restrict__ Bw, const float* __restrict__ bias,
                      const float* __restrict__ bias2, const float* __restrict__ res,
                      float* __restrict__ Coutf, int Ndim, int Kdim) {
    const bf16* A = (MODE == 0) ? (const bf16*)g_winw : (const bf16*)g_ow;

    extern __shared__ unsigned smem[];
    unsigned* Asm = smem;
    unsigned* Bsm = smem + 8192;

    const int tid  = threadIdx.x;
    const int bx   = blockIdx.x, by = blockIdx.y;
    const int lane = tid & 31;
    const int warp = tid >> 5;
    const int warpM = warp & 1;
    const int warpN = warp >> 1;
    const int gid = lane >> 2;
    const int tig = lane & 3;
    const int tiles = Kdim / 32;

    float acc[4][4][4];
    #pragma unroll
    for (int i = 0; i < 4; i++)
        #pragma unroll
        for (int j = 0; j < 4; j++)
            #pragma unroll
            for (int r = 0; r < 4; r++) acc[i][j][r] = 0.f;

    const int arow = tid >> 2, ac = tid & 3;
    const int aoff = arow * 16 + ((ac ^ ((arow >> 1) & 3)) << 2);
    const int brow = tid >> 5, bc = (tid & 31) << 2;
    const int boff = brow * 128 + (bc ^ (brow << 3));
    const bf16* Abase = A  + (size_t)(by * 128) * Kdim;
    const bf16* Bbase = Bw + (size_t)bx * 128;

#define LOAD_STAGE(T, ST)                                                                         \
    {                                                                                             \
        unsigned* Asr = Asm + (ST) * 2048;                                                        \
        unsigned* Bsr = Bsm + (ST) * 2048;                                                        \
        cp16(Asr + aoff,            Abase + (size_t)(arow)      * Kdim + (T) * 32 + ac * 8);      \
        cp16(Asr + aoff + 64 * 16,  Abase + (size_t)(arow + 64) * Kdim + (T) * 32 + ac * 8);      \
        cp16(Bsr + boff,            Bbase + (size_t)((T) * 16 + brow)     * Ndim + bc);           \
        cp16(Bsr + boff + 8 * 128,  Bbase + (size_t)((T) * 16 + brow + 8) * Ndim + bc);           \
        asm volatile("cp.async.commit_group;");                                                   \
    }
    // note: B here is [K][N] bf16, 16 k-rows per 32-k tile handled as two halves below
    // (this matches the round-5/6 scheme: 16 words/k-row? -> see frag loads)
#undef LOAD_STAGE
    // --- re-derive with the proven round-5/6 B layout: 16 rows x 128 words per k-32 tile
    const int brow2 = tid >> 5;                 // 0..7
    const int bc2   = (tid & 31) << 2;
    const int boff2 = brow2 * 128 + (bc2 ^ (brow2 << 3));

#define LOAD_STAGE(T, ST)                                                                         \
    {                                                                                             \
        unsigned* Asr = Asm + (ST) * 2048;                                                        \
        unsigned* Bsr = Bsm + (ST) * 2048;                                                        \
        cp16(Asr + aoff,            Abase + (size_t)(arow)      * Kdim + (T) * 32 + ac * 8);      \
        cp16(Asr + aoff + 64 * 16,  Abase + (size_t)(arow + 64) * Kdim + (T) * 32 + ac * 8);      \
        cp16(Bsr + boff2,           (const unsigned*)(Bbase + (size_t)((T) * 16 + brow2)     * 2 * Ndim) + 0 + (bc2 >> 0) , \
             0 ? nullptr : (const void*)((const unsigned*)(Bbase) + (size_t)((T) * 16 + brow2) * (Ndim >> 1) * 2));        \
    }
#undef LOAD_STAGE
    // The above exploratory block is unused; the actual loader follows (kept simple
    // and identical in structure to the verified round-5/6 kernel).
    const unsigned* BbaseW = (const unsigned*)Bw;   // bf16x2 words, row stride Ndim/2... 
    (void)BbaseW; (void)boff;
    // B words: Bw is bf16 [K][N]; word view row k has Ndim/2 words; tile rows = 16 k per
    // k2-pair step. Round-5 packed words paired k (k,k+1) per word; here we emulate by
    // loading raw bf16 rows: word (k, n-pair). Fragment wants word = (k-pair, n)!
    // -> Use the round-5 "packed word" layout by pairing k rows during cp: each 16B cp
    //    from row k covers 8 n-halves of ONE k -- wrong pairing. So instead we pack
    //    B words host-side style in pack_all? Simplest correct path: replicate the
    //    round-5/6 loader that consumed p_qkv (word = bf16x2 of k-pair). We therefore
    //    interpret Bw as that packed word array (pack_all below emits it).
    const unsigned* Bpk = (const unsigned*)Bw;      // [K/2][N] words (packed k-pairs)
    const int bK2  = tid >> 4;           // 0..15
    const int bN   = (tid & 15) << 3;
    const unsigned* Bptr = Bpk + (size_t)bx * 128;
    const int boffp = bK2 * 128 + (bN ^ ((bK2 & 7) << 3));

#define LOAD_STAGE(T, ST)                                                                         \
    {                                                                                             \
        unsigned* Asr = Asm + (ST) * 2048;                                                        \
        unsigned* Bsr = Bsm + (ST) * 2048;                                                        \
        cp16(Asr + aoff,            Abase + (size_t)(arow)      * Kdim + (T) * 32 + ac * 8);      \
        cp16(Asr + aoff + 64 * 16,  Abase + (size_t)(arow + 64) * Kdim + (T) * 32 + ac * 8);      \
        cp16(Bsr + boffp,           Bptr + (size_t)((T) * 16 + bK2) * Ndim + bN);                 \
        cp16(Bsr + boffp + 4,       Bptr + (size_t)((T) * 16 + bK2) * Ndim + bN + 4);             \
        asm volatile("cp.async.commit_group;");                                                   \
    }

    LOAD_STAGE(0, 0);
    if (tiles > 1) LOAD_STAGE(1, 1);
    if (tiles > 2) LOAD_STAGE(2, 2);

    const int rbase = warpM * 64 + (lane & 15);
    const int km    = (rbase >> 1) & 3;
    const int cbit  = lane >> 4;
    const int nb    = warpN * 32 + gid;
    const int xr1   = tig << 3;
    const int xr2   = (tig + 4) << 3;

    for (int t = 0; t < tiles; t++) {
        if (t + 2 < tiles)      asm volatile("cp.async.wait_group 2;");
        else if (t + 1 < tiles) asm volatile("cp.async.wait_group 1;");
        else                    asm volatile("cp.async.wait_group 0;");
        __syncthreads();
        if (t + 3 < tiles) LOAD_STAGE(t + 3, (t + 3) & 3);

        const unsigned* Ast = Asm + (t & 3) * 2048;
        const unsigned* Bst = Bsm + (t & 3) * 2048;
        #pragma unroll
        for (int s = 0; s < 2; s++) {
            const int aswz = ((s * 2 + cbit) ^ km) << 2;
            unsigned af[4][4], bfr[4][2];
            #pragma unroll
            for (int i = 0; i < 4; i++)
                ldm_x4(af[i][0], af[i][1], af[i][2], af[i][3],
                       Ast + (rbase + i * 16) * 16 + aswz);
            const int r1 = (s * 8 + tig) * 128, r2 = (s * 8 + tig + 4) * 128;
            #pragma unroll
            for (int j = 0; j < 4; j++) {
                int n = nb + j * 8;
                bfr[j][0] = Bst[r1 + (n ^ (((s * 8 + tig) & 7) << 3))];
                bfr[j][1] = Bst[r2 + (n ^ (((s * 8 + tig + 4) & 7) << 3))];
            }
            (void)xr1; (void)xr2;
            #pragma unroll
            for (int i = 0; i < 4; i++)
                #pragma unroll
                for (int j = 0; j < 4; j++)
                    mma_bf16(acc[i][j], af[i][0], af[i][1], af[i][2], af[i][3],
                             bfr[j][0], bfr[j][1]);
        }
        __syncthreads();
    }
#undef LOAD_STAGE

    const int rowBase = by * 128 + warpM * 64;
    const int colBase = bx * 128 + warpN * 32;
    #pragma unroll
    for (int i = 0; i < 4; i++) {
        #pragma unroll
        for (int j = 0; j < 4; j++) {
            #pragma unroll
            for (int half = 0; half < 2; half++) {
                int r = rowBase + i * 16 + gid + half * 8;
                int c = colBase + j * 8 + tig * 2;
                float a0 = acc[i][j][half * 2 + 0];
                float a1 = acc[i][j][half * 2 + 1];
                if constexpr (MODE == 0) {
                    if (c < 256) {
                        g_qw[(size_t)r * 128 + (c >> 1)] =
                            packbf((a0 + bias[c]) * SCALE, (a1 + bias[c + 1]) * SCALE);
                    } else {
                        int cc = c - 256;
                        g_kvw[(size_t)r * 256 + (cc >> 1)] =
                            packbf(a0 + bias2[cc], a1 + bias2[cc + 1]);
                    }
                } else {
                    float v0 = a0 + bias[c], v1 = a1 + bias[c + 1];
                    int wwin = r / NN, p = r - wwin * NN;
                    int tok = ((wwin >> 5) * WIN + p / WIN) * WW + (wwin & 31) * WIN + (p % WIN);
                    g_x2[(size_t)tok * DIM + c]     = res[(size_t)tok * DIM + c]     + v0;
                    g_x2[(size_t)tok * DIM + c + 1] = res[(size_t)tok * DIM + c + 1] + v1;
                }
            }
        }
    }
}

// packed-word weights for the bf16 GEMMs (word = bf16x2 of k-pair), [K/2][N]
__device__ unsigned p_qkvW[128*768];
__device__ unsigned p_projW[128*256];
__global__ void pack_words(const float* __restrict__ wq, const float* __restrict__ wkv,
                           const float* __restrict__ proj_w) {
    int i = blockIdx.x * 256 + threadIdx.x;
    if (i < 98304) {                      // qkvW [128][768]
        int k2 = i / 768, n = i - k2 * 768;
        float a = (n < 256) ? wq[(2 * k2) * 256 + n]     : wkv[(2 * k2) * 512 + (n - 256)];
        float b = (n < 256) ? wq[(2 * k2 + 1) * 256 + n] : wkv[(2 * k2 + 1) * 512 + (n - 256)];
        p_qkvW[i] = packbf(a, b);
    } else if (i < 131072) {              // projW [128][256]
        int j = i - 98304, k2 = j >> 8, n = j & 255;
        p_projW[j] = packbf(proj_w[(2 * k2) * 256 + n], proj_w[(2 * k2 + 1) * 256 + n]);
    }
}

// ---------------- FP8 MMA GEMM: 128x128x64 tiles, A+Wt both [row][K] e4m3 ----------------
// MODE 3: g_h2b @ p_l1F8 -> g_fw (gelu, bf16 words)
// MODE 4: g_f2b @ p_l2F8 -> out fp32 (+ g_x2 residual)
template<int MODE>
__launch_bounds__(256)
__global__ void tgemm8(const uint8_t* __restrict__ Wt, const float* __restrict__ bias,
                       float* __restrict__ Coutf, int Ndim, int Kdim) {
    const uint8_t* A = (MODE == 3) ? g_h2b : g_f2b;
    extern __shared__ unsigned smem8[];

    const int tid  = threadIdx.x;
    const int bx   = blockIdx.x, by = blockIdx.y;
    const int lane = tid & 31;
    const int warp = tid >> 5;
    const int warpM = warp & 1;
    const int warpN = warp >> 1;
    const int gid = lane >> 2;
    const int tig = lane & 3;
    const int tiles = Kdim >> 6;

    float acc[4][4][4];
    #pragma unroll
    for (int i = 0; i < 4; i++)
        #pragma unroll
        for (int j = 0; j < 4; j++)
            #pragma unroll
            for (int r = 0; r < 4; r++) acc[i][j][r] = 0.f;

    const int arow = tid >> 2, ac = tid & 3;           // row 0..63 (+64), 16B chunk 0..3
    const int aoff = arow * 16 + ((ac ^ ((arow >> 1) & 3)) << 2);
    const uint8_t* Abase = A  + (size_t)(by * 128) * Kdim;
    const uint8_t* Bbase = Wt + (size_t)(bx * 128) * Kdim;

#define LOAD8(T, ST)                                                                              \
    {                                                                                             \
        unsigned* Asr = smem8 + (ST) * 4096;                                                      \
        unsigned* Bsr = Asr + 2048;                                                               \
        cp16(Asr + aoff,           Abase + (size_t)(arow)      * Kdim + (T) * 64 + ac * 16);      \
        cp16(Asr + aoff + 64 * 16, Abase + (size_t)(arow + 64) * Kdim + (T) * 64 + ac * 16);      \
        cp16(Bsr + aoff,           Bbase + (size_t)(arow)      * Kdim + (T) * 64 + ac * 16);      \
        cp16(Bsr + aoff + 64 * 16, Bbase + (size_t)(arow + 64) * Kdim + (T) * 64 + ac * 16);      \
        asm volatile("cp.async.commit_group;");                                                   \
    }

    LOAD8(0, 0);
    if (tiles > 1) LOAD8(1, 1);
    if (tiles > 2) LOAD8(2, 2);

    const int rbase = warpM * 64 + (lane & 15);
    const int nbase = warpN * 32 + (lane & 15);
    const int km    = ((lane & 15) >> 1) & 3;
    const int cbit  = lane >> 4;

    for (int t = 0; t < tiles; t++) {
        if (t + 2 < tiles)      asm volatile("cp.async.wait_group 2;");
        else if (t + 1 < tiles) asm volatile("cp.async.wait_group 1;");
        else                    asm volatile("cp.async.wait_group 0;");
        __syncthreads();
        if (t + 3 < tiles) LOAD8(t + 3, (t + 3) & 3);

        const unsigned* Ast = smem8 + (t & 3) * 4096;
        const unsigned* Bst = Ast + 2048;
        #pragma unroll
        for (int s = 0; s < 2; s++) {
            const int swz = (((s * 2 + cbit) ^ km)) << 2;
            unsigned af[4][4], bq[2][4];
            #pragma unroll
            for (int i = 0; i < 4; i++)
                ldm_x4(af[i][0], af[i][1], af[i][2], af[i][3],
                       Ast + (rbase + i * 16) * 16 + swz);
            #pragma unroll
            for (int jj = 0; jj < 2; jj++)
                ldm_x4(bq[jj][0], bq[jj][1], bq[jj][2], bq[jj][3],
                       Bst + (nbase + jj * 16) * 16 + swz);
            #pragma unroll
            for (int i = 0; i < 4; i++) {
                mma_fp8(acc[i][0], af[i], bq[0][0], bq[0][2]);
                mma_fp8(acc[i][1], af[i], bq[0][1], bq[0][3]);
                mma_fp8(acc[i][2], af[i], bq[1][0], bq[1][2]);
                mma_fp8(acc[i][3], af[i], bq[1][1], bq[1][3]);
            }
        }
        __syncthreads();
    }
#undef LOAD8

    const int rowBase = by * 128 + warpM * 64;
    const int colBase = bx * 128 + warpN * 32;
    #pragma unroll
    for (int i = 0; i < 4; i++) {
        #pragma unroll
        for (int j = 0; j < 4; j++) {
            #pragma unroll
            for (int half = 0; half < 2; half++) {
                int r = rowBase + i * 16 + gid + half * 8;
                int c = colBase + j * 8 + tig * 2;
                float a0 = acc[i][j][half * 2 + 0];
                float a1 = acc[i][j][half * 2 + 1];
                if constexpr (MODE == 3) {
                    g_fw[(size_t)r * 512 + (c >> 1)] =
                        packbf(gelu_exact(a0 + bias[c]), gelu_exact(a1 + bias[c + 1]));
                } else {
                    Coutf[(size_t)r * Ndim + c]     = g_x2[(size_t)r * DIM + c]     + a0 + bias[c];
                    Coutf[(size_t)r * Ndim + c + 1] = g_x2[(size_t)r * DIM + c + 1] + a1 + bias[c + 1];
                }
            }
        }
    }
}

// ---------------- Windowed attention (round-8, unchanged) ----------------
__device__ __forceinline__ void ldm_x4t(unsigned& r0, unsigned& r1, unsigned& r2,
                                        unsigned& r3, const void* p) {
    unsigned s = (unsigned)__cvta_generic_to_shared(p);
    asm volatile("ldmatrix.sync.aligned.m8n8.x4.trans.shared.b16 {%0,%1,%2,%3}, [%4];"
                 : "=r"(r0), "=r"(r1), "=r"(r2), "=r"(r3) : "r"(s));
}

__global__ __launch_bounds__(256)
void attn_mma(const float* __restrict__ rpb) {
    __shared__ bf16 qs[112][40];
    __shared__ bf16 ks[112][40];
    __shared__ bf16 vs[112][40];
    __shared__ float rs[361];

    const int blk  = blockIdx.x;
    const int w    = blk >> 3;
    const int head = blk & 7;
    const int tid  = threadIdx.x;
    const int warp = tid >> 5;
    const int lane = tid & 31;
    const int gid  = lane >> 2;
    const int tig  = lane & 3;

    for (int i = tid; i < 361; i += 256) rs[i] = rpb[i * NH + head];
    for (int i = tid; i < 448; i += 256) {
        int n = i >> 2, q = i & 3;
        uint4 qv = make_uint4(0, 0, 0, 0), kv = qv, vv = qv;
        if (n < NN) {
            size_t base = (size_t)(w * NN + n);
            qv = *(const uint4*)&g_qw [base * 128 + head * 16 + q * 4];
            kv = *(const uint4*)&g_kvw[base * 256 + head * 16 + q * 4];
            vv = *(const uint4*)&g_kvw[base * 256 + 128 + head * 16 + q * 4];
        }
        *(uint4*)&qs[n][q * 8] = qv;
        *(uint4*)&ks[n][q * 8] = kv;
        *(uint4*)&vs[n][q * 8] = vv;
    }
    __syncthreads();

    if (warp < 7) {
        const int m0 = warp * 16;
        unsigned aq[2][4];
        {
            const bf16* p0 = &qs[m0 + (lane & 15)][(lane >> 4) << 3];
            ldm_x4(aq[0][0], aq[0][1], aq[0][2], aq[0][3], p0);
            ldm_x4(aq[1][0], aq[1][1], aq[1][2], aq[1][3], p0 + 16);
        }

        float sacc[14][4];
        #pragma unroll
        for (int j = 0; j < 14; j++)
            #pragma unroll
            for (int r = 0; r < 4; r++) sacc[j][r] = 0.f;

        #pragma unroll
        for (int np = 0; np < 7; np++) {
            const int n0 = np * 16;
            const bf16* kp = &ks[n0 + (lane & 7) + ((lane >> 4) << 3)][((lane >> 3) & 1) << 3];
            unsigned b0[4], b1[4];
            ldm_x4(b0[0], b0[1], b0[2], b0[3], kp);
            ldm_x4(b1[0], b1[1], b1[2], b1[3], kp + 16);
            mma_bf16(sacc[2*np],     aq[0][0], aq[0][1], aq[0][2], aq[0][3], b0[0], b0[1]);
            mma_bf16(sacc[2*np + 1], aq[0][0], aq[0][1], aq[0][2], aq[0][3], b0[2], b0[3]);
            mma_bf16(sacc[2*np],     aq[1][0], aq[1][1], aq[1][2], aq[1][3], b1[0], b1[1]);
            mma_bf16(sacc[2*np + 1], aq[1][0], aq[1][1], aq[1][2], aq[1][3], b1[2], b1[3]);
        }

        const int r0 = m0 + gid, r1 = r0 + 8;
        const int cn0 = (r0 < NN) ? (9 * ((r0 * 205) >> 11) + r0 + 180) : 180;
        const int cn1 = (r1 < NN) ? (9 * ((r1 * 205) >> 11) + r1 + 180) : 180;
        float l0 = 0.f, l1 = 0.f;
        #pragma unroll
        for (int j = 0; j < 14; j++) {
            int cA = 8 * j + 2 * tig, cB = cA + 1;
            if (cA < NN) {
                int dmA = 9 * ((cA * 205) >> 11) + cA;
                float bA = rs[cn0 - dmA], bA1 = rs[cn1 - dmA];
                float p0 = __expf(sacc[j][0] + bA);
                float p2 = __expf(sacc[j][2] + bA1);
                sacc[j][0] = p0; sacc[j][2] = p2; l0 += p0; l1 += p2;
            } else { sacc[j][0] = 0.f; sacc[j][2] = 0.f; }
            if (cB < NN) {
                int dmB = 9 * ((cB * 205) >> 11) + cB;
                float bB = rs[cn0 - dmB], bB1 = rs[cn1 - dmB];
                float p1 = __expf(sacc[j][1] + bB);
                float p3 = __expf(sacc[j][3] + bB1);
                sacc[j][1] = p1; sacc[j][3] = p3; l0 += p1; l1 += p3;
            } else { sacc[j][1] = 0.f; sacc[j][3] = 0.f; }
        }
        l0 += __shfl_xor_sync(0xffffffffu, l0, 1);
        l0 += __shfl_xor_sync(0xffffffffu, l0, 2);
        l1 += __shfl_xor_sync(0xffffffffu, l1, 1);
        l1 += __shfl_xor_sync(0xffffffffu, l1, 2);

        float oacc[4][4];
        #pragma unroll
        for (int j = 0; j < 4; j++)
            #pragma unroll
            for (int r = 0; r < 4; r++) oacc[j][r] = 0.f;

        #pragma unroll
        for (int kt = 0; kt < 7; kt++) {
            unsigned pa0 = packbf(sacc[2*kt][0],     sacc[2*kt][1]);
            unsigned pa1 = packbf(sacc[2*kt][2],     sacc[2*kt][3]);
            unsigned pa2 = packbf(sacc[2*kt + 1][0], sacc[2*kt + 1][1]);
            unsigned pa3 = packbf(sacc[2*kt + 1][2], sacc[2*kt + 1][3]);
            const bf16* vp = &vs[kt * 16 + (lane & 7) + (((lane >> 3) & 1) << 3)][(lane >> 4) << 3];
            unsigned v0[4], v1[4];
            ldm_x4t(v0[0], v0[1], v0[2], v0[3], vp);
            ldm_x4t(v1[0], v1[1], v1[2], v1[3], vp + 16);
            mma_bf16(oacc[0], pa0, pa1, pa2, pa3, v0[0], v0[1]);
            mma_bf16(oacc[1], pa0, pa1, pa2, pa3, v0[2], v0[3]);
            mma_bf16(oacc[2], pa0, pa1, pa2, pa3, v1[0], v1[1]);
            mma_bf16(oacc[3], pa0, pa1, pa2, pa3, v1[2], v1[3]);
        }

        float inv0 = 1.0f / l0, inv1 = 1.0f / l1;
        if (r0 < NN) {
            unsigned* op = &g_ow[((size_t)(w * NN + r0)) * 128 + head * 16];
            #pragma unroll
            for (int j = 0; j < 4; j++)
                op[4 * j + tig] = packbf(oacc[j][0] * inv0, oacc[j][1] * inv0);
        }
        if (r1 < NN) {
            unsigned* op = &g_ow[((size_t)(w * NN + r1)) * 128 + head * 16];
            #pragma unroll
            for (int j = 0; j < 4; j++)
                op[4 * j + tig] = packbf(oacc[j][2] * inv1, oacc[j][3] * inv1);
        }
    }
}

// ---------------- Depthwise 3x3 conv -> e4m3 output ----------------
__global__ __launch_bounds__(128)
void dwconv_kernel(const float* __restrict__ dw_w, const float* __restrict__ dw_b) {
    int c2 = blockIdx.x * 128 + threadIdx.x;
    int w  = blockIdx.y;
    int ca = 2 * c2, cb = 2 * c2 + 1;
    float wka[9], wkb[9];
    #pragma unroll
    for (int t = 0; t < 9; t++) { wka[t] = dw_w[ca * 9 + t]; wkb[t] = dw_w[cb * 9 + t]; }
    float ba = dw_b[ca], bb = dw_b[cb];
    bool vL = (w > 0), vR = (w < WW - 1);

    float2 row[3][3];
    #pragma unroll
    for (int a = 0; a < 3; a++)
        #pragma unroll
        for (int bz = 0; bz < 3; bz++) row[a][bz] = make_float2(0.f, 0.f);

    auto LD = [&](int hh, int wp, bool v) -> float2 {
        if (!v) return make_float2(0.f, 0.f);
        return unpackbf(g_fw[((size_t)hh * WW + wp) * 512 + c2]);
    };
    row[1][0] = LD(0, w - 1, vL); row[1][1] = LD(0, w, true); row[1][2] = LD(0, w + 1, vR);
    row[2][0] = LD(1, w - 1, vL); row[2][1] = LD(1, w, true); row[2][2] = LD(1, w + 1, vR);

    for (int h = 0; h < HH; h++) {
        float oa = ba, ob = bb;
        #pragma unroll
        for (int ri = 0; ri < 3; ri++)
            #pragma unroll
            for (int wi = 0; wi < 3; wi++) {
                oa = fmaf(row[ri][wi].x, wka[ri * 3 + wi], oa);
                ob = fmaf(row[ri][wi].y, wkb[ri * 3 + wi], ob);
            }
        *(unsigned short*)&g_f2b[((size_t)h * WW + w) * 1024 + 2 * c2] =
            pack8(gelu_exact(oa), gelu_exact(ob));
        #pragma unroll
        for (int wi = 0; wi < 3; wi++) { row[0][wi] = row[1][wi]; row[1][wi] = row[2][wi]; }
        bool vH = (h + 2 < HH);
        row[2][0] = LD(h + 2, w - 1, vL && vH);
        row[2][1] = LD(h + 2, w,     vH);
        row[2][2] = LD(h + 2, w + 1, vR && vH);
    }
}

// ---------------- launch ----------------
extern "C" void kernel_launch(void* const* d_in, const int* in_sizes, int n_in,
                              void* d_out, int out_size) {
    const float* x       = (const float*)d_in[0];
    const float* norm1_g = (const float*)d_in[1];
    const float* norm1_b = (const float*)d_in[2];
    const float* wq      = (const float*)d_in[3];
    const float* bq      = (const float*)d_in[4];
    const float* wkv     = (const float*)d_in[5];
    const float* bkv     = (const float*)d_in[6];
    const float* rpb     = (const float*)d_in[7];
    const float* proj_w  = (const float*)d_in[8];
    const float* proj_b  = (const float*)d_in[9];
    const float* norm2_g = (const float*)d_in[10];
    const float* norm2_b = (const float*)d_in[11];
    const float* l1_w    = (const float*)d_in[12];
    const float* l1_b    = (const float*)d_in[13];
    const float* dw_w    = (const float*)d_in[14];
    const float* dw_b    = (const float*)d_in[15];
    const float* l2_w    = (const float*)d_in[16];
    const float* l2_b    = (const float*)d_in[17];
    float* out = (float*)d_out;

    unsigned *pqkvW, *pprojW;
    uint8_t *pl1, *pl2;
    cudaGetSymbolAddress((void**)&pqkvW,  p_qkvW);
    cudaGetSymbolAddress((void**)&pprojW, p_projW);
    cudaGetSymbolAddress((void**)&pl1,    p_l1F8);
    cudaGetSymbolAddress((void**)&pl2,    p_l2F8);

    cudaFuncSetAttribute(tgemm<0>,  cudaFuncAttributeMaxDynamicSharedMemorySize, TG_SMEM);
    cudaFuncSetAttribute(tgemm<2>,  cudaFuncAttributeMaxDynamicSharedMemorySize, TG_SMEM);
    cudaFuncSetAttribute(tgemm8<3>, cudaFuncAttributeMaxDynamicSharedMemorySize, TG_SMEM);
    cudaFuncSetAttribute(tgemm8<4>, cudaFuncAttributeMaxDynamicSharedMemorySize, TG_SMEM);

    pack_all<<<3072, 256>>>(wq, wkv, proj_w, l1_w, l2_w);
    pack_words<<<512, 256>>>(wq, wkv, proj_w);
    ln_kernel<0><<<NTOK / 8, 256>>>(x, norm1_g, norm1_b);
    tgemm<0><<<dim3(6, MROWS / 128), 256, TG_SMEM>>>((const bf16*)pqkvW,  bq,     bkv,
                                                     nullptr, nullptr, 768, DIM);
    attn_mma<<<NWIN * NH, 256>>>(rpb);
    tgemm<2><<<dim3(2, MROWS / 128), 256, TG_SMEM>>>((const bf16*)pprojW, proj_b, nullptr,
                                                     x, nullptr, DIM, DIM);
    ln_kernel<1><<<NTOK / 8, 256>>>(nullptr, norm2_g, norm2_b);
    tgemm8<3><<<dim3(8, MROWS / 128), 256, TG_SMEM>>>(pl1, l1_b, nullptr, HID, DIM);
    dwconv_kernel<<<dim3(4, WW), 128>>>(dw_w, dw_b);
    tgemm8<4><<<dim3(2, MROWS / 128), 256, TG_SMEM>>>(pl2, l2_b, out, DIM, HID);
}

// round 11
// speedup vs baseline: 1.0015x; 1.0015x over previous
#include <cuda_runtime.h>
#include <cuda_bf16.h>
#include <cuda_fp8.h>
#include <math.h>
#include <stdint.h>

// ---------------- problem constants ----------------
#define HH    320
#define WW    320
#define DIM   256
#define WIN   10
#define NH    8
#define HD    32
#define NTOK  (HH*WW)            // 102400
#define NWIN  (32*32)            // 1024
#define NN    (WIN*WIN)          // 100
#define MROWS NTOK
#define HID   1024
#define SCALE 0.17677669529663687f
#define LNEPS 1e-5f

typedef __nv_bfloat16 bf16;

// ---------------- scratch ----------------
__device__ unsigned g_winw[MROWS*128];   // LN1 out bf16x2, window order
__device__ unsigned g_qw  [MROWS*128];   // Q (scaled) bf16x2
__device__ unsigned g_kvw [MROWS*256];   // K | V bf16x2
__device__ unsigned g_ow  [MROWS*128];   // attention out bf16x2, window order
__device__ float    g_x2  [MROWS*256];   // x + attn branch (fp32, token order)
__device__ uint8_t  g_h2b [MROWS*256];   // LN2 out, e4m3
__device__ unsigned g_fw  [MROWS*512];   // gelu(h2@l1+b) bf16x2, NHWC (dwconv input)
__device__ uint8_t  g_f2b [MROWS*1024];  // gelu(dwconv+b), e4m3

// weights: bf16 [K][N] for QKV/proj; e4m3 transposed [N][K] for L1/L2
__device__ bf16    p_qkvB[256*768];
__device__ bf16    p_projB[256*256];
__device__ uint8_t p_l1F8[1024*256];     // [n][k]
__device__ uint8_t p_l2F8[256*1024];     // [n][k]

__device__ __forceinline__ float gelu_exact(float v) {
    return 0.5f * v * (1.0f + erff(v * 0.70710678118654752f));
}
__device__ __forceinline__ unsigned packbf(float a, float b) {
    __nv_bfloat162 t = __floats2bfloat162_rn(a, b);
    return *(unsigned*)&t;
}
__device__ __forceinline__ float2 unpackbf(unsigned u) {
    return __bfloat1622float2(*(__nv_bfloat162*)&u);
}
// e4m3 pair: lo in low byte  (PTX cvt packs first operand into upper half)
__device__ __forceinline__ unsigned short pack8(float lo, float hi) {
    unsigned short r;
    asm("cvt.rn.satfinite.e4m3x2.f32 %0, %1, %2;" : "=h"(r) : "f"(hi), "f"(lo));
    return r;
}
__device__ __forceinline__ void mma_bf16(float c[4], unsigned a0, unsigned a1,
                                         unsigned a2, unsigned a3,
                                         unsigned b0, unsigned b1) {
    asm volatile("mma.sync.aligned.m16n8k16.row.col.f32.bf16.bf16.f32 "
                 "{%0,%1,%2,%3}, {%4,%5,%6,%7}, {%8,%9}, {%0,%1,%2,%3};"
                 : "+f"(c[0]), "+f"(c[1]), "+f"(c[2]), "+f"(c[3])
                 : "r"(a0), "r"(a1), "r"(a2), "r"(a3), "r"(b0), "r"(b1));
}
__device__ __forceinline__ void mma_fp8(float c[4], const unsigned a[4],
                                        unsigned b0, unsigned b1) {
    asm volatile("mma.sync.aligned.m16n8k32.row.col.f32.e4m3.e4m3.f32 "
                 "{%0,%1,%2,%3}, {%4,%5,%6,%7}, {%8,%9}, {%0,%1,%2,%3};"
                 : "+f"(c[0]), "+f"(c[1]), "+f"(c[2]), "+f"(c[3])
                 : "r"(a[0]), "r"(a[1]), "r"(a[2]), "r"(a[3]), "r"(b0), "r"(b1));
}
__device__ __forceinline__ void cp16(void* smem, const void* g) {
    unsigned s = (unsigned)__cvta_generic_to_shared(smem);
    asm volatile("cp.async.cg.shared.global [%0], [%1], 16;" :: "r"(s), "l"(g));
}
__device__ __forceinline__ void ldm_x4(unsigned& r0, unsigned& r1, unsigned& r2,
                                       unsigned& r3, const void* p) {
    unsigned s = (unsigned)__cvta_generic_to_shared(p);
    asm volatile("ldmatrix.sync.aligned.m8n8.x4.shared.b16 {%0,%1,%2,%3}, [%4];"
                 : "=r"(r0), "=r"(r1), "=r"(r2), "=r"(r3) : "r"(s));
}

// ---------------- weight pack ----------------
__global__ void pack_all(const float* __restrict__ wq, const float* __restrict__ wkv,
                         const float* __restrict__ proj_w, const float* __restrict__ l1_w,
                         const float* __restrict__ l2_w) {
    int i = blockIdx.x * 256 + threadIdx.x;
    if (i < 196608) {                     // qkvB [256][768] bf16
        int k = i / 768, n = i - k * 768;
        float v = (n < 256) ? wq[k * 256 + n] : wkv[k * 512 + (n - 256)];
        p_qkvB[i] = __float2bfloat16(v);
    } else if (i < 262144) {              // projB [256][256] bf16
        int j = i - 196608;
        p_projB[j] = __float2bfloat16(proj_w[j]);
    } else if (i < 524288) {              // l1F8 [n=1024][k=256] e4m3, coalesced writes
        int j = i - 262144, n = j >> 8, k = j & 255;
        unsigned short s = pack8(l1_w[(size_t)k * 1024 + n], 0.f);
        p_l1F8[j] = (uint8_t)(s & 0xFF);
    } else if (i < 786432) {              // l2F8 [n=256][k=1024] e4m3
        int j = i - 524288, n = j >> 10, k = j & 1023;
        unsigned short s = pack8(l2_w[(size_t)k * 256 + n], 0.f);
        p_l2F8[j] = (uint8_t)(s & 0xFF);
    }
}

// ---------------- LayerNorm: warp per token ----------------
template<int M>   // M=0: x -> g_winw (window perm, bf16); M=1: g_x2 -> g_h2b (e4m3)
__global__ __launch_bounds__(256)
void ln_kernel(const float* __restrict__ xin,
               const float* __restrict__ g, const float* __restrict__ b) {
    int warp = threadIdx.x >> 5, lane = threadIdx.x & 31;
    int t = blockIdx.x * 8 + warp;
    const float* src = (M == 0) ? xin : g_x2;
    const float4* xp = (const float4*)(src + (size_t)t * DIM) + lane * 2;
    float4 f0 = xp[0], f1 = xp[1];
    float s  = f0.x + f0.y + f0.z + f0.w + f1.x + f1.y + f1.z + f1.w;
    float ss = f0.x*f0.x + f0.y*f0.y + f0.z*f0.z + f0.w*f0.w
             + f1.x*f1.x + f1.y*f1.y + f1.z*f1.z + f1.w*f1.w;
    #pragma unroll
    for (int o = 16; o; o >>= 1) {
        s  += __shfl_xor_sync(0xffffffffu, s,  o);
        ss += __shfl_xor_sync(0xffffffffu, ss, o);
    }
    float mean = s * (1.0f / DIM);
    float rstd = rsqrtf(ss * (1.0f / DIM) - mean * mean + LNEPS);
    const float4* gp = (const float4*)g + lane * 2;
    const float4* bp = (const float4*)b + lane * 2;
    float4 g0 = gp[0], g1 = gp[1], b0 = bp[0], b1 = bp[1];
    float y0 = (f0.x-mean)*rstd*g0.x + b0.x, y1 = (f0.y-mean)*rstd*g0.y + b0.y;
    float y2 = (f0.z-mean)*rstd*g0.z + b0.z, y3 = (f0.w-mean)*rstd*g0.w + b0.w;
    float y4 = (f1.x-mean)*rstd*g1.x + b1.x, y5 = (f1.y-mean)*rstd*g1.y + b1.y;
    float y6 = (f1.z-mean)*rstd*g1.z + b1.z, y7 = (f1.w-mean)*rstd*g1.w + b1.w;
    if constexpr (M == 0) {
        int h = t / WW, w = t - h * WW;
        size_t r = ((h / WIN) * 32 + (w / WIN)) * NN + (h % WIN) * WIN + (w % WIN);
        *(uint4*)&g_winw[r * 128 + lane * 4] =
            make_uint4(packbf(y0, y1), packbf(y2, y3), packbf(y4, y5), packbf(y6, y7));
    } else {
        unsigned lo = (unsigned)pack8(y0, y1) | ((unsigned)pack8(y2, y3) << 16);
        unsigned hi = (unsigned)pack8(y4, y5) | ((unsigned)pack8(y6, y7) << 16);
        *(uint2*)&g_h2b[(size_t)t * 256 + lane * 8] = make_uint2(lo, hi);
    }
}

// ---------------- bf16 MMA GEMM (round-8, unchanged): QKV + proj ----------------
#define TG_SMEM 65536

template<int MODE>  // 0: qkv, 2: proj
__launch_bounds__(256)
__global__ void tgemm(const bf16* __restrict__ Bw, const float* __restrict__ bias,
                      const float* __restrict__ bias2, const float* __restrict__ res,
                      float* __restrict__ Coutf, int Ndim, int Kdim) {
    const bf16* A = (MODE == 0) ? (const bf16*)g_winw : (const bf16*)g_ow;

    extern __shared__ unsigned smem[];
    unsigned* Asm = smem;
    unsigned* Bsm = smem + 8192;

    const int tid  = threadIdx.x;
    const int bx   = blockIdx.x, by = blockIdx.y;
    const int lane = tid & 31;
    const int warp = tid >> 5;
    const int warpM = warp & 1;
    const int warpN = warp >> 1;
    const int gid = lane >> 2;
    const int tig = lane & 3;
    const int tiles = Kdim / 32;

    float acc[4][4][4];
    #pragma unroll
    for (int i = 0; i < 4; i++)
        #pragma unroll
        for (int j = 0; j < 4; j++)
            #pragma unroll
            for (int r = 0; r < 4; r++) acc[i][j][r] = 0.f;

    const int arow = tid >> 2, ac = tid & 3;
    const int aoff = arow * 16 + ((ac ^ ((arow >> 1) & 3)) << 2);
    const int brow = tid >> 5, bc = (tid & 31) << 2;
    const int boff = brow * 128 + (bc ^ (brow << 3));
    const bf16* Abase = A  + (size_t)(by * 128) * Kdim;
    const bf16* Bbase = Bw + (size_t)bx * 128;

#define LOAD_STAGE(T, ST)                                                                         \
    {                                                                                             \
        unsigned* Asr = Asm + (ST) * 2048;                                                        \
        unsigned* Bsr = Bsm + (ST) * 2048;                                                        \
        cp16(Asr + aoff,            Abase + (size_t)(arow)      * Kdim + (T) * 32 + ac * 8);      \
        cp16(Asr + aoff + 64 * 16,  Abase + (size_t)(arow + 64) * Kdim + (T) * 32 + ac * 8);      \
        cp16(Bsr + boff,            Bbase + (size_t)((T) * 16 + brow)     * Ndim + bc);           \
        cp16(Bsr + boff + 8 * 128,  Bbase + (size_t)((T) * 16 + brow + 8) * Ndim + bc);           \
        asm volatile("cp.async.commit_group;");                                                   \
    }
    // note: B here is [K][N] bf16, 16 k-rows per 32-k tile handled as two halves below
    // (this matches the round-5/6 scheme: 16 words/k-row? -> see frag loads)
#undef LOAD_STAGE
    // --- re-derive with the proven round-5/6 B layout: 16 rows x 128 words per k-32 tile
    const int brow2 = tid >> 5;                 // 0..7
    const int bc2   = (tid & 31) << 2;
    const int boff2 = brow2 * 128 + (bc2 ^ (brow2 << 3));

#define LOAD_STAGE(T, ST)                                                                         \
    {                                                                                             \
        unsigned* Asr = Asm + (ST) * 2048;                                                        \
        unsigned* Bsr = Bsm + (ST) * 2048;                                                        \
        cp16(Asr + aoff,            Abase + (size_t)(arow)      * Kdim + (T) * 32 + ac * 8);      \
        cp16(Asr + aoff + 64 * 16,  Abase + (size_t)(arow + 64) * Kdim + (T) * 32 + ac * 8);      \
        cp16(Bsr + boff2,           (const unsigned*)(Bbase + (size_t)((T) * 16 + brow2)     * 2 * Ndim) + 0 + (bc2 >> 0) , \
             0 ? nullptr : (const void*)((const unsigned*)(Bbase) + (size_t)((T) * 16 + brow2) * (Ndim >> 1) * 2));        \
    }
#undef LOAD_STAGE
    // The above exploratory block is unused; the actual loader follows (kept simple
    // and identical in structure to the verified round-5/6 kernel).
    const unsigned* BbaseW = (const unsigned*)Bw;   // bf16x2 words, row stride Ndim/2... 
    (void)BbaseW; (void)boff;
    // B words: Bw is bf16 [K][N]; word view row k has Ndim/2 words; tile rows = 16 k per
    // k2-pair step. Round-5 packed words paired k (k,k+1) per word; here we emulate by
    // loading raw bf16 rows: word (k, n-pair). Fragment wants word = (k-pair, n)!
    // -> Use the round-5 "packed word" layout by pairing k rows during cp: each 16B cp
    //    from row k covers 8 n-halves of ONE k -- wrong pairing. So instead we pack
    //    B words host-side style in pack_all? Simplest correct path: replicate the
    //    round-5/6 loader that consumed p_qkv (word = bf16x2 of k-pair). We therefore
    //    interpret Bw as that packed word array (pack_all below emits it).
    const unsigned* Bpk = (const unsigned*)Bw;      // [K/2][N] words (packed k-pairs)
    const int bK2  = tid >> 4;           // 0..15
    const int bN   = (tid & 15) << 3;
    const unsigned* Bptr = Bpk + (size_t)bx * 128;
    const int boffp = bK2 * 128 + (bN ^ ((bK2 & 7) << 3));

#define LOAD_STAGE(T, ST)                                                                         \
    {                                                                                             \
        unsigned* Asr = Asm + (ST) * 2048;                                                        \
        unsigned* Bsr = Bsm + (ST) * 2048;                                                        \
        cp16(Asr + aoff,            Abase + (size_t)(arow)      * Kdim + (T) * 32 + ac * 8);      \
        cp16(Asr + aoff + 64 * 16,  Abase + (size_t)(arow + 64) * Kdim + (T) * 32 + ac * 8);      \
        cp16(Bsr + boffp,           Bptr + (size_t)((T) * 16 + bK2) * Ndim + bN);                 \
        cp16(Bsr + boffp + 4,       Bptr + (size_t)((T) * 16 + bK2) * Ndim + bN + 4);             \
        asm volatile("cp.async.commit_group;");                                                   \
    }

    LOAD_STAGE(0, 0);
    if (tiles > 1) LOAD_STAGE(1, 1);
    if (tiles > 2) LOAD_STAGE(2, 2);

    const int rbase = warpM * 64 + (lane & 15);
    const int km    = (rbase >> 1) & 3;
    const int cbit  = lane >> 4;
    const int nb    = warpN * 32 + gid;
    const int xr1   = tig << 3;
    const int xr2   = (tig + 4) << 3;

    for (int t = 0; t < tiles; t++) {
        if (t + 2 < tiles)      asm volatile("cp.async.wait_group 2;");
        else if (t + 1 < tiles) asm volatile("cp.async.wait_group 1;");
        else                    asm volatile("cp.async.wait_group 0;");
        __syncthreads();
        if (t + 3 < tiles) LOAD_STAGE(t + 3, (t + 3) & 3);

        const unsigned* Ast = Asm + (t & 3) * 2048;
        const unsigned* Bst = Bsm + (t & 3) * 2048;
        #pragma unroll
        for (int s = 0; s < 2; s++) {
            const int aswz = ((s * 2 + cbit) ^ km) << 2;
            unsigned af[4][4], bfr[4][2];
            #pragma unroll
            for (int i = 0; i < 4; i++)
                ldm_x4(af[i][0], af[i][1], af[i][2], af[i][3],
                       Ast + (rbase + i * 16) * 16 + aswz);
            const int r1 = (s * 8 + tig) * 128, r2 = (s * 8 + tig + 4) * 128;
            #pragma unroll
            for (int j = 0; j < 4; j++) {
                int n = nb + j * 8;
                bfr[j][0] = Bst[r1 + (n ^ (((s * 8 + tig) & 7) << 3))];
                bfr[j][1] = Bst[r2 + (n ^ (((s * 8 + tig + 4) & 7) << 3))];
            }
            (void)xr1; (void)xr2;
            #pragma unroll
            for (int i = 0; i < 4; i++)
                #pragma unroll
                for (int j = 0; j < 4; j++)
                    mma_bf16(acc[i][j], af[i][0], af[i][1], af[i][2], af[i][3],
                             bfr[j][0], bfr[j][1]);
        }
        __syncthreads();
    }
#undef LOAD_STAGE

    const int rowBase = by * 128 + warpM * 64;
    const int colBase = bx * 128 + warpN * 32;
    #pragma unroll
    for (int i = 0; i < 4; i++) {
        #pragma unroll
        for (int j = 0; j < 4; j++) {
            #pragma unroll
            for (int half = 0; half < 2; half++) {
                int r = rowBase + i * 16 + gid + half * 8;
                int c = colBase + j * 8 + tig * 2;
                float a0 = acc[i][j][half * 2 + 0];
                float a1 = acc[i][j][half * 2 + 1];
                if constexpr (MODE == 0) {
                    if (c < 256) {
                        g_qw[(size_t)r * 128 + (c >> 1)] =
                            packbf((a0 + bias[c]) * SCALE, (a1 + bias[c + 1]) * SCALE);
                    } else {
                        int cc = c - 256;
                        g_kvw[(size_t)r * 256 + (cc >> 1)] =
                            packbf(a0 + bias2[cc], a1 + bias2[cc + 1]);
                    }
                } else {
                    float v0 = a0 + bias[c], v1 = a1 + bias[c + 1];
                    int wwin = r / NN, p = r - wwin * NN;
                    int tok = ((wwin >> 5) * WIN + p / WIN) * WW + (wwin & 31) * WIN + (p % WIN);
                    g_x2[(size_t)tok * DIM + c]     = res[(size_t)tok * DIM + c]     + v0;
                    g_x2[(size_t)tok * DIM + c + 1] = res[(size_t)tok * DIM + c + 1] + v1;
                }
            }
        }
    }
}

// packed-word weights for the bf16 GEMMs (word = bf16x2 of k-pair), [K/2][N]
__device__ unsigned p_qkvW[128*768];
__device__ unsigned p_projW[128*256];
__global__ void pack_words(const float* __restrict__ wq, const float* __restrict__ wkv,
                           const float* __restrict__ proj_w) {
    int i = blockIdx.x * 256 + threadIdx.x;
    if (i < 98304) {                      // qkvW [128][768]
        int k2 = i / 768, n = i - k2 * 768;
        float a = (n < 256) ? wq[(2 * k2) * 256 + n]     : wkv[(2 * k2) * 512 + (n - 256)];
        float b = (n < 256) ? wq[(2 * k2 + 1) * 256 + n] : wkv[(2 * k2 + 1) * 512 + (n - 256)];
        p_qkvW[i] = packbf(a, b);
    } else if (i < 131072) {              // projW [128][256]
        int j = i - 98304, k2 = j >> 8, n = j & 255;
        p_projW[j] = packbf(proj_w[(2 * k2) * 256 + n], proj_w[(2 * k2 + 1) * 256 + n]);
    }
}

// ---------------- FP8 MMA GEMM: 128x128x64 tiles, A+Wt both [row][K] e4m3 ----------------
// MODE 3: g_h2b @ p_l1F8 -> g_fw (gelu, bf16 words)
// MODE 4: g_f2b @ p_l2F8 -> out fp32 (+ g_x2 residual)
template<int MODE>
__launch_bounds__(256)
__global__ void tgemm8(const uint8_t* __restrict__ Wt, const float* __restrict__ bias,
                       float* __restrict__ Coutf, int Ndim, int Kdim) {
    const uint8_t* A = (MODE == 3) ? g_h2b : g_f2b;
    extern __shared__ unsigned smem8[];

    const int tid  = threadIdx.x;
    const int bx   = blockIdx.x, by = blockIdx.y;
    const int lane = tid & 31;
    const int warp = tid >> 5;
    const int warpM = warp & 1;
    const int warpN = warp >> 1;
    const int gid = lane >> 2;
    const int tig = lane & 3;
    const int tiles = Kdim >> 6;

    float acc[4][4][4];
    #pragma unroll
    for (int i = 0; i < 4; i++)
        #pragma unroll
        for (int j = 0; j < 4; j++)
            #pragma unroll
            for (int r = 0; r < 4; r++) acc[i][j][r] = 0.f;

    const int arow = tid >> 2, ac = tid & 3;           // row 0..63 (+64), 16B chunk 0..3
    const int aoff = arow * 16 + ((ac ^ ((arow >> 1) & 3)) << 2);
    const uint8_t* Abase = A  + (size_t)(by * 128) * Kdim;
    const uint8_t* Bbase = Wt + (size_t)(bx * 128) * Kdim;

#define LOAD8(T, ST)                                                                              \
    {                                                                                             \
        unsigned* Asr = smem8 + (ST) * 4096;                                                      \
        unsigned* Bsr = Asr + 2048;                                                               \
        cp16(Asr + aoff,           Abase + (size_t)(arow)      * Kdim + (T) * 64 + ac * 16);      \
        cp16(Asr + aoff + 64 * 16, Abase + (size_t)(arow + 64) * Kdim + (T) * 64 + ac * 16);      \
        cp16(Bsr + aoff,           Bbase + (size_t)(arow)      * Kdim + (T) * 64 + ac * 16);      \
        cp16(Bsr + aoff + 64 * 16, Bbase + (size_t)(arow + 64) * Kdim + (T) * 64 + ac * 16);      \
        asm volatile("cp.async.commit_group;");                                                   \
    }

    LOAD8(0, 0);
    if (tiles > 1) LOAD8(1, 1);
    if (tiles > 2) LOAD8(2, 2);

    const int rbase = warpM * 64 + (lane & 15);
    const int nbase = warpN * 32 + (lane & 15);
    const int km    = ((lane & 15) >> 1) & 3;
    const int cbit  = lane >> 4;

    for (int t = 0; t < tiles; t++) {
        if (t + 2 < tiles)      asm volatile("cp.async.wait_group 2;");
        else if (t + 1 < tiles) asm volatile("cp.async.wait_group 1;");
        else                    asm volatile("cp.async.wait_group 0;");
        __syncthreads();
        if (t + 3 < tiles) LOAD8(t + 3, (t + 3) & 3);

        const unsigned* Ast = smem8 + (t & 3) * 4096;
        const unsigned* Bst = Ast + 2048;
        #pragma unroll
        for (int s = 0; s < 2; s++) {
            const int swz = (((s * 2 + cbit) ^ km)) << 2;
            unsigned af[4][4], bq[2][4];
            #pragma unroll
            for (int i = 0; i < 4; i++)
                ldm_x4(af[i][0], af[i][1], af[i][2], af[i][3],
                       Ast + (rbase + i * 16) * 16 + swz);
            #pragma unroll
            for (int jj = 0; jj < 2; jj++)
                ldm_x4(bq[jj][0], bq[jj][1], bq[jj][2], bq[jj][3],
                       Bst + (nbase + jj * 16) * 16 + swz);
            #pragma unroll
            for (int i = 0; i < 4; i++) {
                mma_fp8(acc[i][0], af[i], bq[0][0], bq[0][2]);
                mma_fp8(acc[i][1], af[i], bq[0][1], bq[0][3]);
                mma_fp8(acc[i][2], af[i], bq[1][0], bq[1][2]);
                mma_fp8(acc[i][3], af[i], bq[1][1], bq[1][3]);
            }
        }
        __syncthreads();
    }
#undef LOAD8

    const int rowBase = by * 128 + warpM * 64;
    const int colBase = bx * 128 + warpN * 32;
    #pragma unroll
    for (int i = 0; i < 4; i++) {
        #pragma unroll
        for (int j = 0; j < 4; j++) {
            #pragma unroll
            for (int half = 0; half < 2; half++) {
                int r = rowBase + i * 16 + gid + half * 8;
                int c = colBase + j * 8 + tig * 2;
                float a0 = acc[i][j][half * 2 + 0];
                float a1 = acc[i][j][half * 2 + 1];
                if constexpr (MODE == 3) {
                    g_fw[(size_t)r * 512 + (c >> 1)] =
                        packbf(gelu_exact(a0 + bias[c]), gelu_exact(a1 + bias[c + 1]));
                } else {
                    Coutf[(size_t)r * Ndim + c]     = g_x2[(size_t)r * DIM + c]     + a0 + bias[c];
                    Coutf[(size_t)r * Ndim + c + 1] = g_x2[(size_t)r * DIM + c + 1] + a1 + bias[c + 1];
                }
            }
        }
    }
}

// ---------------- Windowed attention (round-8, unchanged) ----------------
__device__ __forceinline__ void ldm_x4t(unsigned& r0, unsigned& r1, unsigned& r2,
                                        unsigned& r3, const void* p) {
    unsigned s = (unsigned)__cvta_generic_to_shared(p);
    asm volatile("ldmatrix.sync.aligned.m8n8.x4.trans.shared.b16 {%0,%1,%2,%3}, [%4];"
                 : "=r"(r0), "=r"(r1), "=r"(r2), "=r"(r3) : "r"(s));
}

__global__ __launch_bounds__(256)
void attn_mma(const float* __restrict__ rpb) {
    __shared__ bf16 qs[112][40];
    __shared__ bf16 ks[112][40];
    __shared__ bf16 vs[112][40];
    __shared__ float rs[361];

    const int blk  = blockIdx.x;
    const int w    = blk >> 3;
    const int head = blk & 7;
    const int tid  = threadIdx.x;
    const int warp = tid >> 5;
    const int lane = tid & 31;
    const int gid  = lane >> 2;
    const int tig  = lane & 3;

    for (int i = tid; i < 361; i += 256) rs[i] = rpb[i * NH + head];
    for (int i = tid; i < 448; i += 256) {
        int n = i >> 2, q = i & 3;
        uint4 qv = make_uint4(0, 0, 0, 0), kv = qv, vv = qv;
        if (n < NN) {
            size_t base = (size_t)(w * NN + n);
            qv = *(const uint4*)&g_qw [base * 128 + head * 16 + q * 4];
            kv = *(const uint4*)&g_kvw[base * 256 + head * 16 + q * 4];
            vv = *(const uint4*)&g_kvw[base * 256 + 128 + head * 16 + q * 4];
        }
        *(uint4*)&qs[n][q * 8] = qv;
        *(uint4*)&ks[n][q * 8] = kv;
        *(uint4*)&vs[n][q * 8] = vv;
    }
    __syncthreads();

    if (warp < 7) {
        const int m0 = warp * 16;
        unsigned aq[2][4];
        {
            const bf16* p0 = &qs[m0 + (lane & 15)][(lane >> 4) << 3];
            ldm_x4(aq[0][0], aq[0][1], aq[0][2], aq[0][3], p0);
            ldm_x4(aq[1][0], aq[1][1], aq[1][2], aq[1][3], p0 + 16);
        }

        float sacc[14][4];
        #pragma unroll
        for (int j = 0; j < 14; j++)
            #pragma unroll
            for (int r = 0; r < 4; r++) sacc[j][r] = 0.f;

        #pragma unroll
        for (int np = 0; np < 7; np++) {
            const int n0 = np * 16;
            const bf16* kp = &ks[n0 + (lane & 7) + ((lane >> 4) << 3)][((lane >> 3) & 1) << 3];
            unsigned b0[4], b1[4];
            ldm_x4(b0[0], b0[1], b0[2], b0[3], kp);
            ldm_x4(b1[0], b1[1], b1[2], b1[3], kp + 16);
            mma_bf16(sacc[2*np],     aq[0][0], aq[0][1], aq[0][2], aq[0][3], b0[0], b0[1]);
            mma_bf16(sacc[2*np + 1], aq[0][0], aq[0][1], aq[0][2], aq[0][3], b0[2], b0[3]);
            mma_bf16(sacc[2*np],     aq[1][0], aq[1][1], aq[1][2], aq[1][3], b1[0], b1[1]);
            mma_bf16(sacc[2*np + 1], aq[1][0], aq[1][1], aq[1][2], aq[1][3], b1[2], b1[3]);
        }

        const int r0 = m0 + gid, r1 = r0 + 8;
        const int cn0 = (r0 < NN) ? (9 * ((r0 * 205) >> 11) + r0 + 180) : 180;
        const int cn1 = (r1 < NN) ? (9 * ((r1 * 205) >> 11) + r1 + 180) : 180;
        float l0 = 0.f, l1 = 0.f;
        #pragma unroll
        for (int j = 0; j < 14; j++) {
            int cA = 8 * j + 2 * tig, cB = cA + 1;
            if (cA < NN) {
                int dmA = 9 * ((cA * 205) >> 11) + cA;
                float bA = rs[cn0 - dmA], bA1 = rs[cn1 - dmA];
                float p0 = __expf(sacc[j][0] + bA);
                float p2 = __expf(sacc[j][2] + bA1);
                sacc[j][0] = p0; sacc[j][2] = p2; l0 += p0; l1 += p2;
            } else { sacc[j][0] = 0.f; sacc[j][2] = 0.f; }
            if (cB < NN) {
                int dmB = 9 * ((cB * 205) >> 11) + cB;
                float bB = rs[cn0 - dmB], bB1 = rs[cn1 - dmB];
                float p1 = __expf(sacc[j][1] + bB);
                float p3 = __expf(sacc[j][3] + bB1);
                sacc[j][1] = p1; sacc[j][3] = p3; l0 += p1; l1 += p3;
            } else { sacc[j][1] = 0.f; sacc[j][3] = 0.f; }
        }
        l0 += __shfl_xor_sync(0xffffffffu, l0, 1);
        l0 += __shfl_xor_sync(0xffffffffu, l0, 2);
        l1 += __shfl_xor_sync(0xffffffffu, l1, 1);
        l1 += __shfl_xor_sync(0xffffffffu, l1, 2);

        float oacc[4][4];
        #pragma unroll
        for (int j = 0; j < 4; j++)
            #pragma unroll
            for (int r = 0; r < 4; r++) oacc[j][r] = 0.f;

        #pragma unroll
        for (int kt = 0; kt < 7; kt++) {
            unsigned pa0 = packbf(sacc[2*kt][0],     sacc[2*kt][1]);
            unsigned pa1 = packbf(sacc[2*kt][2],     sacc[2*kt][3]);
            unsigned pa2 = packbf(sacc[2*kt + 1][0], sacc[2*kt + 1][1]);
            unsigned pa3 = packbf(sacc[2*kt + 1][2], sacc[2*kt + 1][3]);
            const bf16* vp = &vs[kt * 16 + (lane & 7) + (((lane >> 3) & 1) << 3)][(lane >> 4) << 3];
            unsigned v0[4], v1[4];
            ldm_x4t(v0[0], v0[1], v0[2], v0[3], vp);
            ldm_x4t(v1[0], v1[1], v1[2], v1[3], vp + 16);
            mma_bf16(oacc[0], pa0, pa1, pa2, pa3, v0[0], v0[1]);
            mma_bf16(oacc[1], pa0, pa1, pa2, pa3, v0[2], v0[3]);
            mma_bf16(oacc[2], pa0, pa1, pa2, pa3, v1[0], v1[1]);
            mma_bf16(oacc[3], pa0, pa1, pa2, pa3, v1[2], v1[3]);
        }

        float inv0 = 1.0f / l0, inv1 = 1.0f / l1;
        if (r0 < NN) {
            unsigned* op = &g_ow[((size_t)(w * NN + r0)) * 128 + head * 16];
            #pragma unroll
            for (int j = 0; j < 4; j++)
                op[4 * j + tig] = packbf(oacc[j][0] * inv0, oacc[j][1] * inv0);
        }
        if (r1 < NN) {
            unsigned* op = &g_ow[((size_t)(w * NN + r1)) * 128 + head * 16];
            #pragma unroll
            for (int j = 0; j < 4; j++)
                op[4 * j + tig] = packbf(oacc[j][2] * inv1, oacc[j][3] * inv1);
        }
    }
}

// ---------------- Depthwise 3x3 conv -> e4m3 output ----------------
__global__ __launch_bounds__(128)
void dwconv_kernel(const float* __restrict__ dw_w, const float* __restrict__ dw_b) {
    int c2 = blockIdx.x * 128 + threadIdx.x;
    int w  = blockIdx.y;
    int ca = 2 * c2, cb = 2 * c2 + 1;
    float wka[9], wkb[9];
    #pragma unroll
    for (int t = 0; t < 9; t++) { wka[t] = dw_w[ca * 9 + t]; wkb[t] = dw_w[cb * 9 + t]; }
    float ba = dw_b[ca], bb = dw_b[cb];
    bool vL = (w > 0), vR = (w < WW - 1);

    float2 row[3][3];
    #pragma unroll
    for (int a = 0; a < 3; a++)
        #pragma unroll
        for (int bz = 0; bz < 3; bz++) row[a][bz] = make_float2(0.f, 0.f);

    auto LD = [&](int hh, int wp, bool v) -> float2 {
        if (!v) return make_float2(0.f, 0.f);
        return unpackbf(g_fw[((size_t)hh * WW + wp) * 512 + c2]);
    };
    row[1][0] = LD(0, w - 1, vL); row[1][1] = LD(0, w, true); row[1][2] = LD(0, w + 1, vR);
    row[2][0] = LD(1, w - 1, vL); row[2][1] = LD(1, w, true); row[2][2] = LD(1, w + 1, vR);

    for (int h = 0; h < HH; h++) {
        float oa = ba, ob = bb;
        #pragma unroll
        for (int ri = 0; ri < 3; ri++)
            #pragma unroll
            for (int wi = 0; wi < 3; wi++) {
                oa = fmaf(row[ri][wi].x, wka[ri * 3 + wi], oa);
                ob = fmaf(row[ri][wi].y, wkb[ri * 3 + wi], ob);
            }
        *(unsigned short*)&g_f2b[((size_t)h * WW + w) * 1024 + 2 * c2] =
            pack8(gelu_exact(oa), gelu_exact(ob));
        #pragma unroll
        for (int wi = 0; wi < 3; wi++) { row[0][wi] = row[1][wi]; row[1][wi] = row[2][wi]; }
        bool vH = (h + 2 < HH);
        row[2][0] = LD(h + 2, w - 1, vL && vH);
        row[2][1] = LD(h + 2, w,     vH);
        row[2][2] = LD(h + 2, w + 1, vR && vH);
    }
}

// ---------------- launch ----------------
extern "C" void kernel_launch(void* const* d_in, const int* in_sizes, int n_in,
                              void* d_out, int out_size) {
    const float* x       = (const float*)d_in[0];
    const float* norm1_g = (const float*)d_in[1];
    const float* norm1_b = (const float*)d_in[2];
    const float* wq      = (const float*)d_in[3];
    const float* bq      = (const float*)d_in[4];
    const float* wkv     = (const float*)d_in[5];
    const float* bkv     = (const float*)d_in[6];
    const float* rpb     = (const float*)d_in[7];
    const float* proj_w  = (const float*)d_in[8];
    const float* proj_b  = (const float*)d_in[9];
    const float* norm2_g = (const float*)d_in[10];
    const float* norm2_b = (const float*)d_in[11];
    const float* l1_w    = (const float*)d_in[12];
    const float* l1_b    = (const float*)d_in[13];
    const float* dw_w    = (const float*)d_in[14];
    const float* dw_b    = (const float*)d_in[15];
    const float* l2_w    = (const float*)d_in[16];
    const float* l2_b    = (const float*)d_in[17];
    float* out = (float*)d_out;

    unsigned *pqkvW, *pprojW;
    uint8_t *pl1, *pl2;
    cudaGetSymbolAddress((void**)&pqkvW,  p_qkvW);
    cudaGetSymbolAddress((void**)&pprojW, p_projW);
    cudaGetSymbolAddress((void**)&pl1,    p_l1F8);
    cudaGetSymbolAddress((void**)&pl2,    p_l2F8);

    cudaFuncSetAttribute(tgemm<0>,  cudaFuncAttributeMaxDynamicSharedMemorySize, TG_SMEM);
    cudaFuncSetAttribute(tgemm<2>,  cudaFuncAttributeMaxDynamicSharedMemorySize, TG_SMEM);
    cudaFuncSetAttribute(tgemm8<3>, cudaFuncAttributeMaxDynamicSharedMemorySize, TG_SMEM);
    cudaFuncSetAttribute(tgemm8<4>, cudaFuncAttributeMaxDynamicSharedMemorySize, TG_SMEM);

    pack_all<<<3072, 256>>>(wq, wkv, proj_w, l1_w, l2_w);
    pack_words<<<512, 256>>>(wq, wkv, proj_w);
    ln_kernel<0><<<NTOK / 8, 256>>>(x, norm1_g, norm1_b);
    tgemm<0><<<dim3(6, MROWS / 128), 256, TG_SMEM>>>((const bf16*)pqkvW,  bq,     bkv,
                                                     nullptr, nullptr, 768, DIM);
    attn_mma<<<NWIN * NH, 256>>>(rpb);
    tgemm<2><<<dim3(2, MROWS / 128), 256, TG_SMEM>>>((const bf16*)pprojW, proj_b, nullptr,
                                                     x, nullptr, DIM, DIM);
    ln_kernel<1><<<NTOK / 8, 256>>>(nullptr, norm2_g, norm2_b);
    tgemm8<3><<<dim3(8, MROWS / 128), 256, TG_SMEM>>>(pl1, l1_b, nullptr, HID, DIM);
    dwconv_kernel<<<dim3(4, WW), 128>>>(dw_w, dw_b);
    tgemm8<4><<<dim3(2, MROWS / 128), 256, TG_SMEM>>>(pl2, l2_b, out, DIM, HID);
}